// round 1
// baseline (speedup 1.0000x reference)
#include <cuda_runtime.h>
#include <cuda_bf16.h>
#include <cstddef>

// Problem dims
#define BB 32
#define TT 4096
#define DD 512
#define HH 512

// Scratch (device globals; no allocation allowed)
__device__ float g_P[BB * HH];          // hid@W + bias
__device__ float g_c[BB * HH];          // P@Wa + ba
__device__ float g_M[DD * HH];          // U@Wa
__device__ float g_cij[BB * TT];        // pre-softmax scores
__device__ float g_part[BB * 16 * DD];  // weighted-sum partials

// ---------------------------------------------------------------------------
// Small GEMM: out[r][j] = sum_d A[r][d] * Bm[d][j] (+ bias[j]), 8 rows/block,
// 512 threads (one column each). K = 512 fixed.
// ---------------------------------------------------------------------------
__global__ void rowgemm8(const float* __restrict__ A, const float* __restrict__ Bm,
                         const float* __restrict__ bias, float* __restrict__ out)
{
    __shared__ float a[8][512];
    int r0 = blockIdx.x * 8;
    int j  = threadIdx.x;
#pragma unroll
    for (int r = 0; r < 8; r++) a[r][j] = A[(size_t)(r0 + r) * 512 + j];
    __syncthreads();

    float acc[8];
    float bb = bias ? bias[j] : 0.0f;
#pragma unroll
    for (int r = 0; r < 8; r++) acc[r] = bb;

#pragma unroll 4
    for (int d = 0; d < 512; d++) {
        float bv = Bm[(size_t)d * 512 + j];
#pragma unroll
        for (int r = 0; r < 8; r++) acc[r] += a[r][d] * bv;
    }
#pragma unroll
    for (int r = 0; r < 8; r++) out[(size_t)(r0 + r) * 512 + j] = acc[r];
}

// ---------------------------------------------------------------------------
// Main fused kernel: cij[row] = sum_h tanh( (E_row . M[:,h]) + c[b][h] ) * V[h]
// Block: 64 rows (all same b), 256 threads, 64x128 output tile per H-chunk,
// per-thread 4x8 micro-tile. E tile staged transposed in smem (stride 68 pad).
// ---------------------------------------------------------------------------
#define ES_STRIDE 68
#define SMEM_FLOATS (512 * ES_STRIDE + 32 * 128 + 64)

__global__ void __launch_bounds__(256, 1)
attn_main(const float* __restrict__ E, const float* __restrict__ M,
          const float* __restrict__ c, const float* __restrict__ V,
          float* __restrict__ cij)
{
    extern __shared__ float sm[];
    float* Es    = sm;                     // [512][68]  (k-major, row-minor)
    float* Ms    = sm + 512 * ES_STRIDE;   // [32][128]
    float* cij_s = Ms + 32 * 128;          // [64]

    const int tid  = threadIdx.x;
    const int row0 = blockIdx.x * 64;
    const int b    = row0 >> 12;           // row0 / 4096
    const float* Eb = E + (size_t)row0 * 512;

    // Stage E tile transposed: Es[d][r] = E[row0+r][d]
    for (int idx = tid; idx < 64 * 512; idx += 256) {
        int r = idx >> 9;
        int d = idx & 511;
        Es[d * ES_STRIDE + r] = Eb[(size_t)r * 512 + d];
    }
    if (tid < 64) cij_s[tid] = 0.0f;
    __syncthreads();

    const int tx = tid & 15;   // column group: 8 cols each
    const int ty = tid >> 4;   // row group: 4 rows each
    const int r0 = ty * 4;

    for (int h0 = 0; h0 < 512; h0 += 128) {
        float acc[4][8];
#pragma unroll
        for (int i = 0; i < 4; i++)
#pragma unroll
            for (int j = 0; j < 8; j++) acc[i][j] = 0.0f;

        for (int k0 = 0; k0 < 512; k0 += 32) {
            __syncthreads();
            // Load M chunk [k0:k0+32, h0:h0+128]
            for (int idx = tid; idx < 32 * 128; idx += 256) {
                int kk = idx >> 7;
                int h  = idx & 127;
                Ms[kk * 128 + h] = M[(size_t)(k0 + kk) * 512 + (h0 + h)];
            }
            __syncthreads();

#pragma unroll 8
            for (int kk = 0; kk < 32; kk++) {
                float4 a4 = *reinterpret_cast<const float4*>(&Es[(k0 + kk) * ES_STRIDE + r0]);
                float4 b0 = *reinterpret_cast<const float4*>(&Ms[kk * 128 + tx * 8]);
                float4 b1 = *reinterpret_cast<const float4*>(&Ms[kk * 128 + tx * 8 + 4]);
                float av[4] = {a4.x, a4.y, a4.z, a4.w};
                float bv[8] = {b0.x, b0.y, b0.z, b0.w, b1.x, b1.y, b1.z, b1.w};
#pragma unroll
                for (int i = 0; i < 4; i++)
#pragma unroll
                    for (int j = 0; j < 8; j++)
                        acc[i][j] += av[i] * bv[j];
            }
        }

        // Epilogue: tanh(acc + c) * V, reduce over h within this chunk
        const float* cb = c + (size_t)b * 512;
#pragma unroll
        for (int i = 0; i < 4; i++) {
            float rs = 0.0f;
#pragma unroll
            for (int j = 0; j < 8; j++) {
                int hg = h0 + tx * 8 + j;
                rs += tanhf(acc[i][j] + cb[hg]) * V[hg];
            }
            // reduce across the 16 tx lanes (16-wide segments)
#pragma unroll
            for (int off = 8; off > 0; off >>= 1)
                rs += __shfl_down_sync(0xffffffffu, rs, off, 16);
            if (tx == 0) cij_s[r0 + i] += rs;   // single writer per row
        }
    }
    __syncthreads();
    if (tid < 64) cij[row0 + tid] = cij_s[tid];
}

// ---------------------------------------------------------------------------
// Softmax over T per batch row. 32 blocks x 256 threads.
// ---------------------------------------------------------------------------
__global__ void softmax_k(const float* __restrict__ cij, float* __restrict__ alphas)
{
    __shared__ float red[256];
    const int b   = blockIdx.x;
    const int tid = threadIdx.x;
    const float* row = cij + (size_t)b * TT;
    float* arow = alphas + (size_t)b * TT;

    float m = -1e30f;
    for (int t = tid; t < TT; t += 256) m = fmaxf(m, row[t]);
    red[tid] = m; __syncthreads();
    for (int s = 128; s > 0; s >>= 1) {
        if (tid < s) red[tid] = fmaxf(red[tid], red[tid + s]);
        __syncthreads();
    }
    m = red[0];
    __syncthreads();

    float sum = 0.0f;
    for (int t = tid; t < TT; t += 256) {
        float e = expf(row[t] - m);
        arow[t] = e;
        sum += e;
    }
    red[tid] = sum; __syncthreads();
    for (int s = 128; s > 0; s >>= 1) {
        if (tid < s) red[tid] += red[tid + s];
        __syncthreads();
    }
    float inv = 1.0f / red[0];
    __syncthreads();
    for (int t = tid; t < TT; t += 256) arow[t] *= inv;
}

// ---------------------------------------------------------------------------
// Weighted sum: out[b][d] = sum_t E[b][t][d] * alphas[b][t]
// Stage 1: 16 t-chunks per b -> partials (deterministic). Stage 2: reduce.
// ---------------------------------------------------------------------------
__global__ void wsum_partial(const float* __restrict__ E, const float* __restrict__ alphas,
                             float* __restrict__ part)
{
    const int b  = blockIdx.x;
    const int ch = blockIdx.y;
    const int d  = threadIdx.x;  // 512
    const float* Eb = E + ((size_t)b * TT + (size_t)ch * 256) * 512;
    const float* al = alphas + (size_t)b * TT + ch * 256;

    float a0 = 0.f, a1 = 0.f, a2 = 0.f, a3 = 0.f;
#pragma unroll 4
    for (int t = 0; t < 256; t += 4) {
        a0 += Eb[(size_t)(t + 0) * 512 + d] * al[t + 0];
        a1 += Eb[(size_t)(t + 1) * 512 + d] * al[t + 1];
        a2 += Eb[(size_t)(t + 2) * 512 + d] * al[t + 2];
        a3 += Eb[(size_t)(t + 3) * 512 + d] * al[t + 3];
    }
    part[((size_t)b * 16 + ch) * 512 + d] = (a0 + a1) + (a2 + a3);
}

__global__ void wsum_reduce(const float* __restrict__ part, float* __restrict__ out)
{
    const int b = blockIdx.x;
    const int d = threadIdx.x;
    float s = 0.0f;
#pragma unroll
    for (int c = 0; c < 16; c++) s += part[((size_t)b * 16 + c) * 512 + d];
    out[(size_t)b * 512 + d] = s;
}

// ---------------------------------------------------------------------------
// Launch
// ---------------------------------------------------------------------------
extern "C" void kernel_launch(void* const* d_in, const int* in_sizes, int n_in,
                              void* d_out, int out_size)
{
    const float* hid  = (const float*)d_in[0];   // [32,512]
    const float* E    = (const float*)d_in[1];   // [32,4096,512]
    const float* W    = (const float*)d_in[2];   // [512,512]
    const float* U    = (const float*)d_in[3];   // [512,512]
    const float* V    = (const float*)d_in[4];   // [512]
    const float* bias = (const float*)d_in[5];   // [512]
    const float* Wa   = (const float*)d_in[6];   // [512,512]
    const float* ba   = (const float*)d_in[7];   // [512]

    float* out_o = (float*)d_out;                    // [32,512]
    float* out_a = (float*)d_out + BB * DD;          // [32,4096]

    float *P, *c, *M, *cij, *part;
    cudaGetSymbolAddress((void**)&P,    g_P);
    cudaGetSymbolAddress((void**)&c,    g_c);
    cudaGetSymbolAddress((void**)&M,    g_M);
    cudaGetSymbolAddress((void**)&cij,  g_cij);
    cudaGetSymbolAddress((void**)&part, g_part);

    // Allow >48KB dynamic smem for the main kernel (host-side, capture-safe)
    cudaFuncSetAttribute(attn_main, cudaFuncAttributeMaxDynamicSharedMemorySize,
                         SMEM_FLOATS * (int)sizeof(float));

    // P = hid@W + bias   (32 rows)
    rowgemm8<<<BB / 8, 512>>>(hid, W, bias, P);
    // c = P@Wa + ba      (32 rows)
    rowgemm8<<<BB / 8, 512>>>(P, Wa, ba, c);
    // M = U@Wa           (512 rows)
    rowgemm8<<<DD / 8, 512>>>(U, Wa, nullptr, M);

    // cij = reduce_h tanh(E@M + c) * V
    attn_main<<<(BB * TT) / 64, 256, SMEM_FLOATS * (int)sizeof(float)>>>(E, M, c, V, cij);

    // alphas = softmax(cij) -> written straight into d_out's alpha region
    softmax_k<<<BB, 256>>>(cij, out_a);

    // output = E^T @ alphas (deterministic two-stage)
    wsum_partial<<<dim3(BB, 16), 512>>>(E, out_a, part);
    wsum_reduce<<<BB, 512>>>(part, out_o);
}

// round 3
// speedup vs baseline: 3.3736x; 3.3736x over previous
#include <cuda_runtime.h>
#include <cuda_bf16.h>
#include <cstdint>
#include <cstddef>

#define BB 32
#define TT 4096
#define DD 512
#define HH 512

// Scratch (device globals; no allocation allowed)
__device__ float g_P[BB * HH];
__device__ float g_c[BB * HH];
__device__ float g_M[DD * HH];
__device__ __nv_bfloat16 g_Bh[HH * DD];                // bf16 hi of M^T  [h][k]
__device__ __nv_bfloat16 g_Bl[HH * DD];                // bf16 lo of M^T  [h][k]
__device__ __nv_bfloat16 g_Eh[(size_t)BB * TT * DD];   // bf16 hi of E    [row][k]
__device__ __nv_bfloat16 g_El[(size_t)BB * TT * DD];   // bf16 lo of E
__device__ float g_cij[BB * TT];
__device__ float g_part[BB * 16 * DD];

// ---------------------------------------------------------------------------
// PTX helpers (family-portable only: mma.sync + cp.async, no tcgen05)
// ---------------------------------------------------------------------------
__device__ __forceinline__ uint32_t smem_u32(const void* p) {
    uint32_t a;
    asm("{ .reg .u64 t; cvta.to.shared.u64 t, %1; cvt.u32.u64 %0, t; }" : "=r"(a) : "l"(p));
    return a;
}
__device__ __forceinline__ void cpa16(uint32_t dst, const void* src) {
    asm volatile("cp.async.cg.shared.global [%0], [%1], 16;" :: "r"(dst), "l"(src));
}
#define CPA_COMMIT() asm volatile("cp.async.commit_group;" ::: "memory")
#define CPA_WAIT0()  asm volatile("cp.async.wait_group 0;" ::: "memory")

__device__ __forceinline__ void mma16816(float* d, const uint32_t* a, const uint32_t* b) {
    asm volatile(
        "mma.sync.aligned.m16n8k16.row.col.f32.bf16.bf16.f32 "
        "{%0,%1,%2,%3}, {%4,%5,%6,%7}, {%8,%9}, {%0,%1,%2,%3};"
        : "+f"(d[0]), "+f"(d[1]), "+f"(d[2]), "+f"(d[3])
        : "r"(a[0]), "r"(a[1]), "r"(a[2]), "r"(a[3]), "r"(b[0]), "r"(b[1]));
}

// ---------------------------------------------------------------------------
// Small GEMM: out[r][j] = sum_d A[r][d]*Bm[d][j] (+bias[j]); 16 rows/block.
// ---------------------------------------------------------------------------
__global__ void rowgemm16(const float* __restrict__ A, const float* __restrict__ Bm,
                          const float* __restrict__ bias, float* __restrict__ out)
{
    __shared__ float a[16][512];
    int r0 = blockIdx.x * 16;
    int j  = threadIdx.x;
#pragma unroll
    for (int r = 0; r < 16; r++) a[r][j] = A[(size_t)(r0 + r) * 512 + j];
    __syncthreads();

    float acc[16];
    float bb = bias ? bias[j] : 0.0f;
#pragma unroll
    for (int r = 0; r < 16; r++) acc[r] = bb;
#pragma unroll 4
    for (int d = 0; d < 512; d++) {
        float bv = Bm[(size_t)d * 512 + j];
#pragma unroll
        for (int r = 0; r < 16; r++) acc[r] += a[r][d] * bv;
    }
#pragma unroll
    for (int r = 0; r < 16; r++) out[(size_t)(r0 + r) * 512 + j] = acc[r];
}

// ---------------------------------------------------------------------------
// Transpose+split M (fp32 [k][h]) -> Bh/Bl (bf16 [h][k])
// ---------------------------------------------------------------------------
__global__ void conv_M(const float* __restrict__ Mf,
                       __nv_bfloat16* __restrict__ Bh, __nv_bfloat16* __restrict__ Bl)
{
    __shared__ float t[32][33];
    int k0 = blockIdx.x * 32, h0 = blockIdx.y * 32;
    int tx = threadIdx.x, ty = threadIdx.y;  // 32 x 8
#pragma unroll
    for (int i = 0; i < 32; i += 8)
        t[ty + i][tx] = Mf[(size_t)(k0 + ty + i) * 512 + h0 + tx];
    __syncthreads();
#pragma unroll
    for (int i = 0; i < 32; i += 8) {
        float v = t[tx][ty + i];
        __nv_bfloat16 h = __float2bfloat16(v);
        __nv_bfloat16 l = __float2bfloat16(v - __bfloat162float(h));
        size_t o = (size_t)(h0 + ty + i) * 512 + (k0 + tx);
        Bh[o] = h;
        Bl[o] = l;
    }
}

// ---------------------------------------------------------------------------
// Split E (fp32) -> Eh/El (bf16), same [row][k] layout. 4 elems/thread.
// ---------------------------------------------------------------------------
__global__ void conv_E(const float* __restrict__ E,
                       __nv_bfloat16* __restrict__ Eh, __nv_bfloat16* __restrict__ El)
{
    size_t i = ((size_t)blockIdx.x * 256 + threadIdx.x) * 4;
    float4 f = *(const float4*)(E + i);
    __nv_bfloat162 h01 = __floats2bfloat162_rn(f.x, f.y);
    __nv_bfloat162 h23 = __floats2bfloat162_rn(f.z, f.w);
    float2 hf01 = __bfloat1622float2(h01);
    float2 hf23 = __bfloat1622float2(h23);
    __nv_bfloat162 l01 = __floats2bfloat162_rn(f.x - hf01.x, f.y - hf01.y);
    __nv_bfloat162 l23 = __floats2bfloat162_rn(f.z - hf23.x, f.w - hf23.y);
    *(uint2*)((char*)Eh + i * 2) = make_uint2(*(uint32_t*)&h01, *(uint32_t*)&h23);
    *(uint2*)((char*)El + i * 2) = make_uint2(*(uint32_t*)&l01, *(uint32_t*)&l23);
}

// ---------------------------------------------------------------------------
// Main mma.sync kernel:
// cij[row] = sum_h tanh( (E@M)[row,h] + c[b][h] ) * V[h]
// CTA: 128 rows x 128 h per pass (4 passes). K in 32-chunks, double-buffered
// cp.async. Split bf16: acc += Eh*Mh + El*Mh + Eh*Ml (fp32 HMMA accum).
// ---------------------------------------------------------------------------
#define TILE_B  10240            /* 128 rows x 80B (40 bf16, k-chunk=32 padded) */
#define OFF_CS  81920
#define OFF_VS  83968
#define OFF_EP  86016
#define OFF_CIJ 87040
#define SMEM_BYTES 87552

__device__ __forceinline__ void load_chunk(
    uint32_t sb, int buf, const __nv_bfloat16* EbH, const __nv_bfloat16* EbL,
    const __nv_bfloat16* BtH, const __nv_bfloat16* BtL,
    int h0, int k0, int tid)
{
    const __nv_bfloat16* srcs[4] = { EbH, EbL, BtH + (size_t)h0 * 512, BtL + (size_t)h0 * 512 };
#pragma unroll
    for (int t = 0; t < 8; t++) {
        int i = tid + t * 256;             // 0..2047
        int tile = i >> 9;                 // 0..3
        int s = i & 511;
        int row = s >> 2, seg = s & 3;
        const __nv_bfloat16* src = srcs[tile] + (size_t)row * 512 + k0 + seg * 8;
        uint32_t dst = sb + (uint32_t)((buf * 4 + tile) * TILE_B + row * 80 + seg * 16);
        cpa16(dst, src);
    }
}

__global__ void __launch_bounds__(256, 2)
attn_mma(const __nv_bfloat16* __restrict__ EhG, const __nv_bfloat16* __restrict__ ElG,
         const __nv_bfloat16* __restrict__ BtH, const __nv_bfloat16* __restrict__ BtL,
         const float* __restrict__ c, const float* __restrict__ V,
         float* __restrict__ cij)
{
    extern __shared__ char sm[];
    const uint32_t sb = smem_u32(sm);
    const int tid = threadIdx.x, wid = tid >> 5, lane = tid & 31;
    const int warp_m = wid & 3;            // 4 m-groups of 32 rows
    const int warp_n = wid >> 2;           // 2 n-groups of 64 cols
    const int lq = lane >> 2, lr = lane & 3;
    const int row0 = blockIdx.x * 128;
    const int b = row0 >> 12;

    const __nv_bfloat16* EbH = EhG + (size_t)row0 * 512;
    const __nv_bfloat16* EbL = ElG + (size_t)row0 * 512;

    float* c_s   = (float*)(sm + OFF_CS);
    float* V_s   = (float*)(sm + OFF_VS);
    float* ep_s  = (float*)(sm + OFF_EP);
    float* cij_s = (float*)(sm + OFF_CIJ);

    for (int i = tid; i < 512; i += 256) {
        c_s[i] = c[(size_t)b * 512 + i];
        V_s[i] = V[i];
    }
    if (tid < 128) cij_s[tid] = 0.0f;
    __syncthreads();

    for (int hp = 0; hp < 4; hp++) {
        const int h0 = hp * 128;
        float acc[2][8][4];
#pragma unroll
        for (int fm = 0; fm < 2; fm++)
#pragma unroll
            for (int fn = 0; fn < 8; fn++)
#pragma unroll
                for (int j = 0; j < 4; j++) acc[fm][fn][j] = 0.0f;

        load_chunk(sb, 0, EbH, EbL, BtH, BtL, h0, 0, tid);
        CPA_COMMIT();

        for (int kc = 0; kc < 16; kc++) {
            const int buf = kc & 1;
            CPA_WAIT0();
            __syncthreads();
            if (kc < 15) {
                load_chunk(sb, buf ^ 1, EbH, EbL, BtH, BtL, h0, (kc + 1) * 32, tid);
                CPA_COMMIT();
            }

            const char* ah = sm + (buf * 4 + 0) * TILE_B;
            const char* al = sm + (buf * 4 + 1) * TILE_B;
            const char* bh = sm + (buf * 4 + 2) * TILE_B;
            const char* bl = sm + (buf * 4 + 3) * TILE_B;

#pragma unroll
            for (int ks = 0; ks < 2; ks++) {
                uint32_t aH[2][4], aL[2][4];
#pragma unroll
                for (int fm = 0; fm < 2; fm++) {
                    int row = warp_m * 32 + fm * 16 + lq;
                    int cb = lr * 2 + ks * 16;
                    const char* pa = ah + row * 80 + cb * 2;
                    aH[fm][0] = *(const uint32_t*)(pa);
                    aH[fm][1] = *(const uint32_t*)(pa + 8 * 80);
                    aH[fm][2] = *(const uint32_t*)(pa + 16);
                    aH[fm][3] = *(const uint32_t*)(pa + 8 * 80 + 16);
                    const char* pl = al + row * 80 + cb * 2;
                    aL[fm][0] = *(const uint32_t*)(pl);
                    aL[fm][1] = *(const uint32_t*)(pl + 8 * 80);
                    aL[fm][2] = *(const uint32_t*)(pl + 16);
                    aL[fm][3] = *(const uint32_t*)(pl + 8 * 80 + 16);
                }
#pragma unroll
                for (int fn = 0; fn < 8; fn++) {
                    int n = warp_n * 64 + fn * 8 + lq;
                    int kb = lr * 2 + ks * 16;
                    const char* pb = bh + n * 80 + kb * 2;
                    const char* pc = bl + n * 80 + kb * 2;
                    uint32_t bH[2], bL[2];
                    bH[0] = *(const uint32_t*)(pb);
                    bH[1] = *(const uint32_t*)(pb + 16);
                    bL[0] = *(const uint32_t*)(pc);
                    bL[1] = *(const uint32_t*)(pc + 16);
#pragma unroll
                    for (int fm = 0; fm < 2; fm++) {
                        mma16816(acc[fm][fn], aH[fm], bH);
                        mma16816(acc[fm][fn], aL[fm], bH);
                        mma16816(acc[fm][fn], aH[fm], bL);
                    }
                }
            }
            __syncthreads();
        }

        // ---- epilogue for this h-pass ----
        float rsum[4] = {0.f, 0.f, 0.f, 0.f};
#pragma unroll
        for (int fm = 0; fm < 2; fm++)
#pragma unroll
            for (int fn = 0; fn < 8; fn++) {
                int h = h0 + warp_n * 64 + fn * 8 + lr * 2;
                float v0 = tanhf(acc[fm][fn][0] + c_s[h])     * V_s[h];
                float v1 = tanhf(acc[fm][fn][1] + c_s[h + 1]) * V_s[h + 1];
                float v2 = tanhf(acc[fm][fn][2] + c_s[h])     * V_s[h];
                float v3 = tanhf(acc[fm][fn][3] + c_s[h + 1]) * V_s[h + 1];
                rsum[fm * 2]     += v0 + v1;
                rsum[fm * 2 + 1] += v2 + v3;
            }
#pragma unroll
        for (int j = 0; j < 4; j++) {
            rsum[j] += __shfl_xor_sync(0xffffffffu, rsum[j], 1);
            rsum[j] += __shfl_xor_sync(0xffffffffu, rsum[j], 2);
        }
        if (lr == 0) {
#pragma unroll
            for (int fm = 0; fm < 2; fm++) {
                int r = warp_m * 32 + fm * 16 + lq;
                ep_s[warp_n * 128 + r]     = rsum[fm * 2];
                ep_s[warp_n * 128 + r + 8] = rsum[fm * 2 + 1];
            }
        }
        __syncthreads();
        if (tid < 128) cij_s[tid] += ep_s[tid] + ep_s[128 + tid];
        __syncthreads();
    }

    if (tid < 128) cij[row0 + tid] = cij_s[tid];
}

// ---------------------------------------------------------------------------
// Softmax over T per batch row
// ---------------------------------------------------------------------------
__global__ void softmax_k(const float* __restrict__ cij, float* __restrict__ alphas)
{
    __shared__ float red[256];
    const int b = blockIdx.x, tid = threadIdx.x;
    const float* row = cij + (size_t)b * TT;
    float* arow = alphas + (size_t)b * TT;

    float m = -1e30f;
    for (int t = tid; t < TT; t += 256) m = fmaxf(m, row[t]);
    red[tid] = m; __syncthreads();
    for (int s = 128; s > 0; s >>= 1) {
        if (tid < s) red[tid] = fmaxf(red[tid], red[tid + s]);
        __syncthreads();
    }
    m = red[0];
    __syncthreads();

    float sum = 0.0f;
    for (int t = tid; t < TT; t += 256) {
        float e = expf(row[t] - m);
        arow[t] = e;
        sum += e;
    }
    red[tid] = sum; __syncthreads();
    for (int s = 128; s > 0; s >>= 1) {
        if (tid < s) red[tid] += red[tid + s];
        __syncthreads();
    }
    float inv = 1.0f / red[0];
    __syncthreads();
    for (int t = tid; t < TT; t += 256) arow[t] *= inv;
}

// ---------------------------------------------------------------------------
// Weighted sum (deterministic two-stage)
// ---------------------------------------------------------------------------
__global__ void wsum_partial(const float* __restrict__ E, const float* __restrict__ alphas,
                             float* __restrict__ part)
{
    const int b = blockIdx.x, ch = blockIdx.y, d = threadIdx.x;
    const float* Eb = E + ((size_t)b * TT + (size_t)ch * 256) * 512;
    const float* al = alphas + (size_t)b * TT + ch * 256;

    float a0 = 0.f, a1 = 0.f, a2 = 0.f, a3 = 0.f;
#pragma unroll 4
    for (int t = 0; t < 256; t += 4) {
        a0 += Eb[(size_t)(t + 0) * 512 + d] * al[t + 0];
        a1 += Eb[(size_t)(t + 1) * 512 + d] * al[t + 1];
        a2 += Eb[(size_t)(t + 2) * 512 + d] * al[t + 2];
        a3 += Eb[(size_t)(t + 3) * 512 + d] * al[t + 3];
    }
    part[((size_t)b * 16 + ch) * 512 + d] = (a0 + a1) + (a2 + a3);
}

__global__ void wsum_reduce(const float* __restrict__ part, float* __restrict__ out)
{
    const int b = blockIdx.x, d = threadIdx.x;
    float s = 0.0f;
#pragma unroll
    for (int c2 = 0; c2 < 16; c2++) s += part[((size_t)b * 16 + c2) * 512 + d];
    out[(size_t)b * 512 + d] = s;
}

// ---------------------------------------------------------------------------
// Launch
// ---------------------------------------------------------------------------
extern "C" void kernel_launch(void* const* d_in, const int* in_sizes, int n_in,
                              void* d_out, int out_size)
{
    const float* hid  = (const float*)d_in[0];
    const float* E    = (const float*)d_in[1];
    const float* W    = (const float*)d_in[2];
    const float* U    = (const float*)d_in[3];
    const float* V    = (const float*)d_in[4];
    const float* bias = (const float*)d_in[5];
    const float* Wa   = (const float*)d_in[6];
    const float* ba   = (const float*)d_in[7];

    float* out_o = (float*)d_out;
    float* out_a = (float*)d_out + BB * DD;

    float *P, *c, *Mf, *cijp, *part;
    __nv_bfloat16 *Bh, *Bl, *Eh, *El;
    cudaGetSymbolAddress((void**)&P,    g_P);
    cudaGetSymbolAddress((void**)&c,    g_c);
    cudaGetSymbolAddress((void**)&Mf,   g_M);
    cudaGetSymbolAddress((void**)&Bh,   g_Bh);
    cudaGetSymbolAddress((void**)&Bl,   g_Bl);
    cudaGetSymbolAddress((void**)&Eh,   g_Eh);
    cudaGetSymbolAddress((void**)&El,   g_El);
    cudaGetSymbolAddress((void**)&cijp, g_cij);
    cudaGetSymbolAddress((void**)&part, g_part);

    cudaFuncSetAttribute(attn_mma, cudaFuncAttributeMaxDynamicSharedMemorySize, SMEM_BYTES);

    rowgemm16<<<BB / 16, 512>>>(hid, W, bias, P);     // P = hid@W + bias
    rowgemm16<<<BB / 16, 512>>>(P, Wa, ba, c);        // c = P@Wa + ba
    rowgemm16<<<DD / 16, 512>>>(U, Wa, nullptr, Mf);  // M = U@Wa
    conv_M<<<dim3(16, 16), dim3(32, 8)>>>(Mf, Bh, Bl);
    conv_E<<<(int)(((size_t)BB * TT * DD) / 1024), 256>>>(E, Eh, El);

    attn_mma<<<(BB * TT) / 128, 256, SMEM_BYTES>>>(Eh, El, Bh, Bl, c, V, cijp);

    softmax_k<<<BB, 256>>>(cijp, out_a);
    wsum_partial<<<dim3(BB, 16), 512>>>(E, out_a, part);
    wsum_reduce<<<BB, 512>>>(part, out_o);
}

// round 5
// speedup vs baseline: 3.5982x; 1.0666x over previous
#include <cuda_runtime.h>
#include <cuda_bf16.h>
#include <cstdint>
#include <cstddef>

#define BB 32
#define TT 4096
#define DD 512
#define HH 512

// Scratch (device globals; no allocation allowed)
__device__ float g_P[BB * HH];
__device__ float g_c[BB * HH];
__device__ float g_M[DD * HH];
__device__ __nv_bfloat16 g_Bh[HH * DD];   // bf16 hi of M^T  [h][k]
__device__ __nv_bfloat16 g_Bl[HH * DD];   // bf16 lo of M^T  [h][k]
__device__ float g_cij[BB * TT];
__device__ float g_part[BB * 16 * DD];

// ---------------------------------------------------------------------------
// PTX helpers (family-portable only: mma.sync + cp.async, no tcgen05)
// ---------------------------------------------------------------------------
__device__ __forceinline__ uint32_t smem_u32(const void* p) {
    uint32_t a;
    asm("{ .reg .u64 t; cvta.to.shared.u64 t, %1; cvt.u32.u64 %0, t; }" : "=r"(a) : "l"(p));
    return a;
}
__device__ __forceinline__ void cpa16(uint32_t dst, const void* src) {
    asm volatile("cp.async.cg.shared.global [%0], [%1], 16;" :: "r"(dst), "l"(src));
}
#define CPA_COMMIT() asm volatile("cp.async.commit_group;" ::: "memory")
#define CPA_WAIT0()  asm volatile("cp.async.wait_group 0;" ::: "memory")

__device__ __forceinline__ float tanh_fast(float x) {
    float y;
    asm("tanh.approx.f32 %0, %1;" : "=f"(y) : "f"(x));
    return y;
}

__device__ __forceinline__ void mma16816(float* d, const uint32_t* a, const uint32_t* b) {
    asm volatile(
        "mma.sync.aligned.m16n8k16.row.col.f32.bf16.bf16.f32 "
        "{%0,%1,%2,%3}, {%4,%5,%6,%7}, {%8,%9}, {%0,%1,%2,%3};"
        : "+f"(d[0]), "+f"(d[1]), "+f"(d[2]), "+f"(d[3])
        : "r"(a[0]), "r"(a[1]), "r"(a[2]), "r"(a[3]), "r"(b[0]), "r"(b[1]));
}

// ---------------------------------------------------------------------------
// Small GEMM: out[r][j] = sum_d A[r][d]*Bm[d][j] (+bias[j]); 16 rows/block.
// ---------------------------------------------------------------------------
__global__ void rowgemm16(const float* __restrict__ A, const float* __restrict__ Bm,
                          const float* __restrict__ bias, float* __restrict__ out)
{
    __shared__ float a[16][512];
    int r0 = blockIdx.x * 16;
    int j  = threadIdx.x;
#pragma unroll
    for (int r = 0; r < 16; r++) a[r][j] = A[(size_t)(r0 + r) * 512 + j];
    __syncthreads();

    float acc[16];
    float bb = bias ? bias[j] : 0.0f;
#pragma unroll
    for (int r = 0; r < 16; r++) acc[r] = bb;
#pragma unroll 4
    for (int d = 0; d < 512; d++) {
        float bv = Bm[(size_t)d * 512 + j];
#pragma unroll
        for (int r = 0; r < 16; r++) acc[r] += a[r][d] * bv;
    }
#pragma unroll
    for (int r = 0; r < 16; r++) out[(size_t)(r0 + r) * 512 + j] = acc[r];
}

// ---------------------------------------------------------------------------
// Transpose+split M (fp32 [k][h]) -> Bh/Bl (bf16 [h][k])
// ---------------------------------------------------------------------------
__global__ void conv_M(const float* __restrict__ Mf,
                       __nv_bfloat16* __restrict__ Bh, __nv_bfloat16* __restrict__ Bl)
{
    __shared__ float t[32][33];
    int k0 = blockIdx.x * 32, h0 = blockIdx.y * 32;
    int tx = threadIdx.x, ty = threadIdx.y;  // 32 x 8
#pragma unroll
    for (int i = 0; i < 32; i += 8)
        t[ty + i][tx] = Mf[(size_t)(k0 + ty + i) * 512 + h0 + tx];
    __syncthreads();
#pragma unroll
    for (int i = 0; i < 32; i += 8) {
        float v = t[tx][ty + i];
        __nv_bfloat16 h = __float2bfloat16(v);
        __nv_bfloat16 l = __float2bfloat16(v - __bfloat162float(h));
        size_t o = (size_t)(h0 + ty + i) * 512 + (k0 + tx);
        Bh[o] = h;
        Bl[o] = l;
    }
}

// ---------------------------------------------------------------------------
// Main mma.sync kernel (E converted inline):
// cij[row] = sum_h tanh( (E@M)[row,h] + c[b][h] ) * V[h]
// CTA: 128 rows x 128 h per pass (4 passes). K in 32-chunks.
// E fp32 staged via cp.async (single buffer), split to bf16 hi/lo in smem.
// B (M^T bf16 hi/lo) double-buffered cp.async.
// acc += Eh*Mh + El*Mh + Eh*Ml (fp32 HMMA accum).
// ---------------------------------------------------------------------------
#define TILE_B  10240            /* 128 rows x 80B */
#define OFF_EF  0                /* fp32 E staging: 128 x 32 floats = 16384 */
#define OFF_AH  16384
#define OFF_AL  26624
#define OFF_BH  36864            /* + buf*10240, 2 bufs */
#define OFF_BL  57344            /* + buf*10240, 2 bufs */
#define OFF_CS  77824
#define OFF_VS  79872
#define OFF_EP  81920
#define OFF_CIJ 82944
#define SMEM_BYTES 83456

__device__ __forceinline__ void load_E_chunk(uint32_t sb, const float* Eb, int k0, int tid)
{
#pragma unroll
    for (int j = 0; j < 4; j++) {
        int u = tid + j * 256;             // 0..1023 float4 units
        int row = u >> 3, seg = u & 7;
        cpa16(sb + OFF_EF + (uint32_t)(u * 16), Eb + (size_t)row * 512 + k0 + seg * 4);
    }
}

__device__ __forceinline__ void load_B_chunk(
    uint32_t sb, int buf, const __nv_bfloat16* BtH, const __nv_bfloat16* BtL,
    int h0, int k0, int tid)
{
#pragma unroll
    for (int j = 0; j < 4; j++) {
        int u = tid + j * 256;             // 0..1023: tile = u>>9 (0=bh,1=bl)
        int tile = u >> 9;
        int s = u & 511;
        int row = s >> 2, seg = s & 3;
        const __nv_bfloat16* src = (tile ? BtL : BtH) + (size_t)(h0 + row) * 512 + k0 + seg * 8;
        uint32_t dst = sb + (tile ? OFF_BL : OFF_BH) + (uint32_t)(buf * TILE_B + row * 80 + seg * 16);
        cpa16(dst, src);
    }
}

__global__ void __launch_bounds__(256, 2)
attn_mma(const float* __restrict__ E,
         const __nv_bfloat16* __restrict__ BtH, const __nv_bfloat16* __restrict__ BtL,
         const float* __restrict__ c, const float* __restrict__ V,
         float* __restrict__ cij)
{
    extern __shared__ char sm[];
    const uint32_t sb = smem_u32(sm);
    const int tid = threadIdx.x, wid = tid >> 5, lane = tid & 31;
    const int warp_m = wid & 3;            // 4 m-groups of 32 rows
    const int warp_n = wid >> 2;           // 2 n-groups of 64 cols
    const int lq = lane >> 2, lr = lane & 3;
    const int row0 = blockIdx.x * 128;
    const int b = row0 >> 12;

    const float* Eb = E + (size_t)row0 * 512;

    float* Ef    = (float*)(sm + OFF_EF);
    float* c_s   = (float*)(sm + OFF_CS);
    float* V_s   = (float*)(sm + OFF_VS);
    float* ep_s  = (float*)(sm + OFF_EP);
    float* cij_s = (float*)(sm + OFF_CIJ);

    for (int i = tid; i < 512; i += 256) {
        c_s[i] = c[(size_t)b * 512 + i];
        V_s[i] = V[i];
    }
    if (tid < 128) cij_s[tid] = 0.0f;
    __syncthreads();

    for (int hp = 0; hp < 4; hp++) {
        const int h0 = hp * 128;
        float acc[2][8][4];
#pragma unroll
        for (int fm = 0; fm < 2; fm++)
#pragma unroll
            for (int fn = 0; fn < 8; fn++)
#pragma unroll
                for (int j = 0; j < 4; j++) acc[fm][fn][j] = 0.0f;

        load_E_chunk(sb, Eb, 0, tid);
        load_B_chunk(sb, 0, BtH, BtL, h0, 0, tid);
        CPA_COMMIT();

        for (int kc = 0; kc < 16; kc++) {
            const int buf = kc & 1;
            CPA_WAIT0();
            __syncthreads();

            // Convert fp32 E chunk -> bf16 hi/lo in smem (80B-stride layout)
            {
                char* ah = sm + OFF_AH;
                char* al = sm + OFF_AL;
#pragma unroll
                for (int j = 0; j < 4; j++) {
                    int u = tid + j * 256;
                    int row = u >> 3, seg = u & 7;
                    float4 f = *(const float4*)(Ef + u * 4);
                    __nv_bfloat162 h01 = __floats2bfloat162_rn(f.x, f.y);
                    __nv_bfloat162 h23 = __floats2bfloat162_rn(f.z, f.w);
                    float2 hf01 = __bfloat1622float2(h01);
                    float2 hf23 = __bfloat1622float2(h23);
                    __nv_bfloat162 l01 = __floats2bfloat162_rn(f.x - hf01.x, f.y - hf01.y);
                    __nv_bfloat162 l23 = __floats2bfloat162_rn(f.z - hf23.x, f.w - hf23.y);
                    uint32_t off = (uint32_t)(row * 80 + seg * 8);
                    *(uint2*)(ah + off) = make_uint2(*(uint32_t*)&h01, *(uint32_t*)&h23);
                    *(uint2*)(al + off) = make_uint2(*(uint32_t*)&l01, *(uint32_t*)&l23);
                }
            }
            __syncthreads();

            if (kc < 15) {
                load_E_chunk(sb, Eb, (kc + 1) * 32, tid);
                load_B_chunk(sb, buf ^ 1, BtH, BtL, h0, (kc + 1) * 32, tid);
                CPA_COMMIT();
            }

            const char* ah = sm + OFF_AH;
            const char* al = sm + OFF_AL;
            const char* bh = sm + OFF_BH + buf * TILE_B;
            const char* bl = sm + OFF_BL + buf * TILE_B;

#pragma unroll
            for (int ks = 0; ks < 2; ks++) {
                uint32_t aH[2][4], aL[2][4];
#pragma unroll
                for (int fm = 0; fm < 2; fm++) {
                    int row = warp_m * 32 + fm * 16 + lq;
                    int cb = lr * 2 + ks * 16;
                    const char* pa = ah + row * 80 + cb * 2;
                    aH[fm][0] = *(const uint32_t*)(pa);
                    aH[fm][1] = *(const uint32_t*)(pa + 8 * 80);
                    aH[fm][2] = *(const uint32_t*)(pa + 16);
                    aH[fm][3] = *(const uint32_t*)(pa + 8 * 80 + 16);
                    const char* pl = al + row * 80 + cb * 2;
                    aL[fm][0] = *(const uint32_t*)(pl);
                    aL[fm][1] = *(const uint32_t*)(pl + 8 * 80);
                    aL[fm][2] = *(const uint32_t*)(pl + 16);
                    aL[fm][3] = *(const uint32_t*)(pl + 8 * 80 + 16);
                }
#pragma unroll
                for (int fn = 0; fn < 8; fn++) {
                    int n = warp_n * 64 + fn * 8 + lq;
                    int kb = lr * 2 + ks * 16;
                    const char* pb = bh + n * 80 + kb * 2;
                    const char* pc = bl + n * 80 + kb * 2;
                    uint32_t bH[2], bL[2];
                    bH[0] = *(const uint32_t*)(pb);
                    bH[1] = *(const uint32_t*)(pb + 16);
                    bL[0] = *(const uint32_t*)(pc);
                    bL[1] = *(const uint32_t*)(pc + 16);
#pragma unroll
                    for (int fm = 0; fm < 2; fm++) {
                        mma16816(acc[fm][fn], aH[fm], bH);
                        mma16816(acc[fm][fn], aL[fm], bH);
                        mma16816(acc[fm][fn], aH[fm], bL);
                    }
                }
            }
            __syncthreads();
        }

        // ---- epilogue for this h-pass (MUFU.TANH) ----
        float rsum[4] = {0.f, 0.f, 0.f, 0.f};
#pragma unroll
        for (int fm = 0; fm < 2; fm++)
#pragma unroll
            for (int fn = 0; fn < 8; fn++) {
                int h = h0 + warp_n * 64 + fn * 8 + lr * 2;
                float v0 = tanh_fast(acc[fm][fn][0] + c_s[h])     * V_s[h];
                float v1 = tanh_fast(acc[fm][fn][1] + c_s[h + 1]) * V_s[h + 1];
                float v2 = tanh_fast(acc[fm][fn][2] + c_s[h])     * V_s[h];
                float v3 = tanh_fast(acc[fm][fn][3] + c_s[h + 1]) * V_s[h + 1];
                rsum[fm * 2]     += v0 + v1;
                rsum[fm * 2 + 1] += v2 + v3;
            }
#pragma unroll
        for (int j = 0; j < 4; j++) {
            rsum[j] += __shfl_xor_sync(0xffffffffu, rsum[j], 1);
            rsum[j] += __shfl_xor_sync(0xffffffffu, rsum[j], 2);
        }
        if (lr == 0) {
#pragma unroll
            for (int fm = 0; fm < 2; fm++) {
                int r = warp_m * 32 + fm * 16 + lq;
                ep_s[warp_n * 128 + r]     = rsum[fm * 2];
                ep_s[warp_n * 128 + r + 8] = rsum[fm * 2 + 1];
            }
        }
        __syncthreads();
        if (tid < 128) cij_s[tid] += ep_s[tid] + ep_s[128 + tid];
        __syncthreads();
    }

    if (tid < 128) cij[row0 + tid] = cij_s[tid];
}

// ---------------------------------------------------------------------------
// Softmax over T per batch row
// ---------------------------------------------------------------------------
__global__ void softmax_k(const float* __restrict__ cij, float* __restrict__ alphas)
{
    __shared__ float red[256];
    const int b = blockIdx.x, tid = threadIdx.x;
    const float* row = cij + (size_t)b * TT;
    float* arow = alphas + (size_t)b * TT;

    float m = -1e30f;
    for (int t = tid; t < TT; t += 256) m = fmaxf(m, row[t]);
    red[tid] = m; __syncthreads();
    for (int s = 128; s > 0; s >>= 1) {
        if (tid < s) red[tid] = fmaxf(red[tid], red[tid + s]);
        __syncthreads();
    }
    m = red[0];
    __syncthreads();

    float sum = 0.0f;
    for (int t = tid; t < TT; t += 256) {
        float e = expf(row[t] - m);
        arow[t] = e;
        sum += e;
    }
    red[tid] = sum; __syncthreads();
    for (int s = 128; s > 0; s >>= 1) {
        if (tid < s) red[tid] += red[tid + s];
        __syncthreads();
    }
    float inv = 1.0f / red[0];
    __syncthreads();
    for (int t = tid; t < TT; t += 256) arow[t] *= inv;
}

// ---------------------------------------------------------------------------
// Weighted sum (deterministic two-stage)
// ---------------------------------------------------------------------------
__global__ void wsum_partial(const float* __restrict__ E, const float* __restrict__ alphas,
                             float* __restrict__ part)
{
    const int b = blockIdx.x, ch = blockIdx.y, d = threadIdx.x;
    const float* Eb = E + ((size_t)b * TT + (size_t)ch * 256) * 512;
    const float* al = alphas + (size_t)b * TT + ch * 256;

    float a0 = 0.f, a1 = 0.f, a2 = 0.f, a3 = 0.f;
#pragma unroll 4
    for (int t = 0; t < 256; t += 4) {
        a0 += Eb[(size_t)(t + 0) * 512 + d] * al[t + 0];
        a1 += Eb[(size_t)(t + 1) * 512 + d] * al[t + 1];
        a2 += Eb[(size_t)(t + 2) * 512 + d] * al[t + 2];
        a3 += Eb[(size_t)(t + 3) * 512 + d] * al[t + 3];
    }
    part[((size_t)b * 16 + ch) * 512 + d] = (a0 + a1) + (a2 + a3);
}

__global__ void wsum_reduce(const float* __restrict__ part, float* __restrict__ out)
{
    const int b = blockIdx.x, d = threadIdx.x;
    float s = 0.0f;
#pragma unroll
    for (int c2 = 0; c2 < 16; c2++) s += part[((size_t)b * 16 + c2) * 512 + d];
    out[(size_t)b * 512 + d] = s;
}

// ---------------------------------------------------------------------------
// Launch
// ---------------------------------------------------------------------------
extern "C" void kernel_launch(void* const* d_in, const int* in_sizes, int n_in,
                              void* d_out, int out_size)
{
    const float* hid  = (const float*)d_in[0];
    const float* E    = (const float*)d_in[1];
    const float* W    = (const float*)d_in[2];
    const float* U    = (const float*)d_in[3];
    const float* V    = (const float*)d_in[4];
    const float* bias = (const float*)d_in[5];
    const float* Wa   = (const float*)d_in[6];
    const float* ba   = (const float*)d_in[7];

    float* out_o = (float*)d_out;
    float* out_a = (float*)d_out + BB * DD;

    float *P, *c, *Mf, *cijp, *part;
    __nv_bfloat16 *Bh, *Bl;
    cudaGetSymbolAddress((void**)&P,    g_P);
    cudaGetSymbolAddress((void**)&c,    g_c);
    cudaGetSymbolAddress((void**)&Mf,   g_M);
    cudaGetSymbolAddress((void**)&Bh,   g_Bh);
    cudaGetSymbolAddress((void**)&Bl,   g_Bl);
    cudaGetSymbolAddress((void**)&cijp, g_cij);
    cudaGetSymbolAddress((void**)&part, g_part);

    cudaFuncSetAttribute(attn_mma, cudaFuncAttributeMaxDynamicSharedMemorySize, SMEM_BYTES);

    rowgemm16<<<BB / 16, 512>>>(hid, W, bias, P);     // P = hid@W + bias
    rowgemm16<<<BB / 16, 512>>>(P, Wa, ba, c);        // c = P@Wa + ba
    rowgemm16<<<DD / 16, 512>>>(U, Wa, nullptr, Mf);  // M = U@Wa
    conv_M<<<dim3(16, 16), dim3(32, 8)>>>(Mf, Bh, Bl);

    attn_mma<<<(BB * TT) / 128, 256, SMEM_BYTES>>>(E, Bh, Bl, c, V, cijp);

    softmax_k<<<BB, 256>>>(cijp, out_a);
    wsum_partial<<<dim3(BB, 16), 512>>>(E, out_a, part);
    wsum_reduce<<<BB, 512>>>(part, out_o);
}

// round 6
// speedup vs baseline: 4.7096x; 1.3089x over previous
#include <cuda_runtime.h>
#include <cuda_fp16.h>
#include <cstdint>
#include <cstddef>

#define BB 32
#define TT 4096
#define DD 512
#define HH 512

// Scratch (device globals; no allocation allowed)
__device__ float g_P[BB * HH];
__device__ float g_c[BB * HH];
__device__ __half g_BhT[HH * DD];   // fp16 M^T  [h][k]
__device__ float g_cij[BB * TT];
__device__ float g_part[BB * 16 * DD];

// ---------------------------------------------------------------------------
// PTX helpers (family-portable: mma.sync + cp.async + ldmatrix)
// ---------------------------------------------------------------------------
__device__ __forceinline__ uint32_t smem_u32(const void* p) {
    uint32_t a;
    asm("{ .reg .u64 t; cvta.to.shared.u64 t, %1; cvt.u32.u64 %0, t; }" : "=r"(a) : "l"(p));
    return a;
}
__device__ __forceinline__ void cpa16(uint32_t dst, const void* src) {
    asm volatile("cp.async.cg.shared.global [%0], [%1], 16;" :: "r"(dst), "l"(src));
}
#define CPA_COMMIT() asm volatile("cp.async.commit_group;" ::: "memory")
#define CPA_WAIT0()  asm volatile("cp.async.wait_group 0;" ::: "memory")

__device__ __forceinline__ float tanh_fast(float x) {
    float y;
    asm("tanh.approx.f32 %0, %1;" : "=f"(y) : "f"(x));
    return y;
}

__device__ __forceinline__ void ldm_x4(uint32_t* r, uint32_t addr) {
    asm volatile("ldmatrix.sync.aligned.m8n8.x4.shared.b16 {%0,%1,%2,%3}, [%4];"
                 : "=r"(r[0]), "=r"(r[1]), "=r"(r[2]), "=r"(r[3]) : "r"(addr));
}
__device__ __forceinline__ void ldm_x2(uint32_t* r, uint32_t addr) {
    asm volatile("ldmatrix.sync.aligned.m8n8.x2.shared.b16 {%0,%1}, [%2];"
                 : "=r"(r[0]), "=r"(r[1]) : "r"(addr));
}

__device__ __forceinline__ void mma16816h(float* d, const uint32_t* a, const uint32_t* b) {
    asm volatile(
        "mma.sync.aligned.m16n8k16.row.col.f32.f16.f16.f32 "
        "{%0,%1,%2,%3}, {%4,%5,%6,%7}, {%8,%9}, {%0,%1,%2,%3};"
        : "+f"(d[0]), "+f"(d[1]), "+f"(d[2]), "+f"(d[3])
        : "r"(a[0]), "r"(a[1]), "r"(a[2]), "r"(a[3]), "r"(b[0]), "r"(b[1]));
}

// ---------------------------------------------------------------------------
// Small GEMM: out[r][j] = sum_d A[r][d]*Bm[d][j] (+bias[j]); 16 rows/block.
// ---------------------------------------------------------------------------
__global__ void rowgemm16(const float* __restrict__ A, const float* __restrict__ Bm,
                          const float* __restrict__ bias, float* __restrict__ out)
{
    __shared__ float a[16][512];
    int r0 = blockIdx.x * 16;
    int j  = threadIdx.x;
#pragma unroll
    for (int r = 0; r < 16; r++) a[r][j] = A[(size_t)(r0 + r) * 512 + j];
    __syncthreads();

    float acc[16];
    float bb = bias ? bias[j] : 0.0f;
#pragma unroll
    for (int r = 0; r < 16; r++) acc[r] = bb;
#pragma unroll 4
    for (int d = 0; d < 512; d++) {
        float bv = Bm[(size_t)d * 512 + j];
#pragma unroll
        for (int r = 0; r < 16; r++) acc[r] += a[r][d] * bv;
    }
#pragma unroll
    for (int r = 0; r < 16; r++) out[(size_t)(r0 + r) * 512 + j] = acc[r];
}

// ---------------------------------------------------------------------------
// M-GEMM with fused transpose + fp16 convert: outT[h][k] = fp16((U@Wa)[k][h])
// ---------------------------------------------------------------------------
__global__ void rowgemmMh(const float* __restrict__ A, const float* __restrict__ Bm,
                          __half* __restrict__ outT)
{
    __shared__ float a[16][512];
    int r0 = blockIdx.x * 16;   // r = k index
    int j  = threadIdx.x;       // j = h index
#pragma unroll
    for (int r = 0; r < 16; r++) a[r][j] = A[(size_t)(r0 + r) * 512 + j];
    __syncthreads();

    float acc[16];
#pragma unroll
    for (int r = 0; r < 16; r++) acc[r] = 0.0f;
#pragma unroll 4
    for (int d = 0; d < 512; d++) {
        float bv = Bm[(size_t)d * 512 + j];
#pragma unroll
        for (int r = 0; r < 16; r++) acc[r] += a[r][d] * bv;
    }
#pragma unroll
    for (int r = 0; r < 16; r++)
        outT[(size_t)j * 512 + (r0 + r)] = __float2half_rn(acc[r]);
}

// ---------------------------------------------------------------------------
// Main mma.sync kernel:
// cij[row] = sum_h tanh( (E@M)[row,h] + c[b][h] ) * V[h]
// CTA: 128 rows x 128 h per pass (4 passes). K in 32-chunks.
// E fp32 staged via cp.async, split to fp16 hi/lo in smem (exact 2-term).
// B = fp16(M^T), single term, double-buffered cp.async.
// acc += Eh*Mh + El*Mh  (== E*Mh exactly, fp32 HMMA accum).
// ---------------------------------------------------------------------------
#define TILE_B  10240            /* 128 rows x 80B */
#define OFF_EF  0                /* fp32 E staging: 128 x 32 floats = 16384 */
#define OFF_AH  16384
#define OFF_AL  26624
#define OFF_B   36864            /* + buf*10240, 2 bufs -> end 57344 */
#define OFF_CS  57344
#define OFF_VS  59392
#define OFF_EP  61440
#define OFF_CIJ 62464
#define SMEM_BYTES 62976

__device__ __forceinline__ void load_E_chunk(uint32_t sb, const float* Eb, int k0, int tid)
{
#pragma unroll
    for (int j = 0; j < 4; j++) {
        int u = tid + j * 256;             // 0..1023 float4 units
        int row = u >> 3, seg = u & 7;
        cpa16(sb + OFF_EF + (uint32_t)(u * 16), Eb + (size_t)row * 512 + k0 + seg * 4);
    }
}

__device__ __forceinline__ void load_B_chunk(
    uint32_t sb, int buf, const __half* Bt, int h0, int k0, int tid)
{
#pragma unroll
    for (int j = 0; j < 2; j++) {
        int u = tid + j * 256;             // 0..511
        int row = u >> 2, seg = u & 3;
        const __half* src = Bt + (size_t)(h0 + row) * 512 + k0 + seg * 8;
        uint32_t dst = sb + OFF_B + (uint32_t)(buf * TILE_B + row * 80 + seg * 16);
        cpa16(dst, src);
    }
}

__global__ void __launch_bounds__(256, 2)
attn_mma(const float* __restrict__ E, const __half* __restrict__ Bt,
         const float* __restrict__ c, const float* __restrict__ V,
         float* __restrict__ cij)
{
    extern __shared__ char sm[];
    const uint32_t sb = smem_u32(sm);
    const int tid = threadIdx.x, wid = tid >> 5, lane = tid & 31;
    const int warp_m = wid & 3;            // 4 m-groups of 32 rows
    const int warp_n = wid >> 2;           // 2 n-groups of 64 cols
    const int lq = lane >> 2, lr = lane & 3;
    const int row0 = blockIdx.x * 128;
    const int b = row0 >> 12;

    const float* Eb = E + (size_t)row0 * 512;

    float* Ef    = (float*)(sm + OFF_EF);
    float* c_s   = (float*)(sm + OFF_CS);
    float* V_s   = (float*)(sm + OFF_VS);
    float* ep_s  = (float*)(sm + OFF_EP);
    float* cij_s = (float*)(sm + OFF_CIJ);

    for (int i = tid; i < 512; i += 256) {
        c_s[i] = c[(size_t)b * 512 + i];
        V_s[i] = V[i];
    }
    if (tid < 128) cij_s[tid] = 0.0f;
    __syncthreads();

    // ldmatrix base addresses (per-lane)
    const int amat = lane >> 3, arr = lane & 7;   // A: mat 0..3, row-in-mat

    for (int hp = 0; hp < 4; hp++) {
        const int h0 = hp * 128;
        float acc[2][8][4];
#pragma unroll
        for (int fm = 0; fm < 2; fm++)
#pragma unroll
            for (int fn = 0; fn < 8; fn++)
#pragma unroll
                for (int j = 0; j < 4; j++) acc[fm][fn][j] = 0.0f;

        load_E_chunk(sb, Eb, 0, tid);
        load_B_chunk(sb, 0, Bt, h0, 0, tid);
        CPA_COMMIT();

        for (int kc = 0; kc < 16; kc++) {
            const int buf = kc & 1;
            CPA_WAIT0();
            __syncthreads();

            // Convert fp32 E chunk -> fp16 hi/lo in smem (80B-stride layout)
            {
                char* ah = sm + OFF_AH;
                char* al = sm + OFF_AL;
#pragma unroll
                for (int j = 0; j < 4; j++) {
                    int u = tid + j * 256;
                    int row = u >> 3, seg = u & 7;
                    float4 f = *(const float4*)(Ef + u * 4);
                    __half2 h01 = __float22half2_rn(make_float2(f.x, f.y));
                    __half2 h23 = __float22half2_rn(make_float2(f.z, f.w));
                    float2 hf01 = __half22float2(h01);
                    float2 hf23 = __half22float2(h23);
                    __half2 l01 = __float22half2_rn(make_float2(f.x - hf01.x, f.y - hf01.y));
                    __half2 l23 = __float22half2_rn(make_float2(f.z - hf23.x, f.w - hf23.y));
                    uint32_t off = (uint32_t)(row * 80 + seg * 8);
                    *(uint2*)(ah + off) = make_uint2(*(uint32_t*)&h01, *(uint32_t*)&h23);
                    *(uint2*)(al + off) = make_uint2(*(uint32_t*)&l01, *(uint32_t*)&l23);
                }
            }
            __syncthreads();

            if (kc < 15) {
                load_E_chunk(sb, Eb, (kc + 1) * 32, tid);
                load_B_chunk(sb, buf ^ 1, Bt, h0, (kc + 1) * 32, tid);
                CPA_COMMIT();
            }

            const uint32_t bbase = sb + OFF_B + (uint32_t)(buf * TILE_B);

#pragma unroll
            for (int ks = 0; ks < 2; ks++) {
                // A fragments via ldmatrix x4: mats (m0-7,k0-7),(m8-15,k0-7),(m0-7,k8-15),(m8-15,k8-15)
                uint32_t aH[2][4], aL[2][4];
#pragma unroll
                for (int fm = 0; fm < 2; fm++) {
                    int arow = warp_m * 32 + fm * 16 + (amat & 1) * 8 + arr;
                    uint32_t aoff = (uint32_t)(arow * 80 + ks * 32 + (amat >> 1) * 16);
                    ldm_x4(aH[fm], sb + OFF_AH + aoff);
                    ldm_x4(aL[fm], sb + OFF_AL + aoff);
                }
#pragma unroll
                for (int fn = 0; fn < 8; fn++) {
                    // B fragment via ldmatrix x2: mats (n0-7,k0-7),(n0-7,k8-15)
                    int brow = warp_n * 64 + fn * 8 + arr;
                    uint32_t boff = (uint32_t)(brow * 80 + ks * 32 + (amat & 1) * 16);
                    uint32_t bF[2];
                    ldm_x2(bF, bbase + boff);
#pragma unroll
                    for (int fm = 0; fm < 2; fm++) {
                        mma16816h(acc[fm][fn], aH[fm], bF);
                        mma16816h(acc[fm][fn], aL[fm], bF);
                    }
                }
            }
            __syncthreads();
        }

        // ---- epilogue for this h-pass (MUFU.TANH) ----
        float rsum[4] = {0.f, 0.f, 0.f, 0.f};
#pragma unroll
        for (int fm = 0; fm < 2; fm++)
#pragma unroll
            for (int fn = 0; fn < 8; fn++) {
                int h = h0 + warp_n * 64 + fn * 8 + lr * 2;
                float v0 = tanh_fast(acc[fm][fn][0] + c_s[h])     * V_s[h];
                float v1 = tanh_fast(acc[fm][fn][1] + c_s[h + 1]) * V_s[h + 1];
                float v2 = tanh_fast(acc[fm][fn][2] + c_s[h])     * V_s[h];
                float v3 = tanh_fast(acc[fm][fn][3] + c_s[h + 1]) * V_s[h + 1];
                rsum[fm * 2]     += v0 + v1;
                rsum[fm * 2 + 1] += v2 + v3;
            }
#pragma unroll
        for (int j = 0; j < 4; j++) {
            rsum[j] += __shfl_xor_sync(0xffffffffu, rsum[j], 1);
            rsum[j] += __shfl_xor_sync(0xffffffffu, rsum[j], 2);
        }
        if (lr == 0) {
#pragma unroll
            for (int fm = 0; fm < 2; fm++) {
                int r = warp_m * 32 + fm * 16 + lq;
                ep_s[warp_n * 128 + r]     = rsum[fm * 2];
                ep_s[warp_n * 128 + r + 8] = rsum[fm * 2 + 1];
            }
        }
        __syncthreads();
        if (tid < 128) cij_s[tid] += ep_s[tid] + ep_s[128 + tid];
        __syncthreads();
    }

    if (tid < 128) cij[row0 + tid] = cij_s[tid];
}

// ---------------------------------------------------------------------------
// Softmax over T per batch row
// ---------------------------------------------------------------------------
__global__ void softmax_k(const float* __restrict__ cij, float* __restrict__ alphas)
{
    __shared__ float red[256];
    const int b = blockIdx.x, tid = threadIdx.x;
    const float* row = cij + (size_t)b * TT;
    float* arow = alphas + (size_t)b * TT;

    float m = -1e30f;
    for (int t = tid; t < TT; t += 256) m = fmaxf(m, row[t]);
    red[tid] = m; __syncthreads();
    for (int s = 128; s > 0; s >>= 1) {
        if (tid < s) red[tid] = fmaxf(red[tid], red[tid + s]);
        __syncthreads();
    }
    m = red[0];
    __syncthreads();

    float sum = 0.0f;
    for (int t = tid; t < TT; t += 256) {
        float e = expf(row[t] - m);
        arow[t] = e;
        sum += e;
    }
    red[tid] = sum; __syncthreads();
    for (int s = 128; s > 0; s >>= 1) {
        if (tid < s) red[tid] += red[tid + s];
        __syncthreads();
    }
    float inv = 1.0f / red[0];
    __syncthreads();
    for (int t = tid; t < TT; t += 256) arow[t] *= inv;
}

// ---------------------------------------------------------------------------
// Weighted sum (deterministic two-stage)
// ---------------------------------------------------------------------------
__global__ void wsum_partial(const float* __restrict__ E, const float* __restrict__ alphas,
                             float* __restrict__ part)
{
    const int b = blockIdx.x, ch = blockIdx.y, d = threadIdx.x;
    const float* Eb = E + ((size_t)b * TT + (size_t)ch * 256) * 512;
    const float* al = alphas + (size_t)b * TT + ch * 256;

    float a0 = 0.f, a1 = 0.f, a2 = 0.f, a3 = 0.f;
#pragma unroll 4
    for (int t = 0; t < 256; t += 4) {
        a0 += Eb[(size_t)(t + 0) * 512 + d] * al[t + 0];
        a1 += Eb[(size_t)(t + 1) * 512 + d] * al[t + 1];
        a2 += Eb[(size_t)(t + 2) * 512 + d] * al[t + 2];
        a3 += Eb[(size_t)(t + 3) * 512 + d] * al[t + 3];
    }
    part[((size_t)b * 16 + ch) * 512 + d] = (a0 + a1) + (a2 + a3);
}

__global__ void wsum_reduce(const float* __restrict__ part, float* __restrict__ out)
{
    const int b = blockIdx.x, d = threadIdx.x;
    float s = 0.0f;
#pragma unroll
    for (int c2 = 0; c2 < 16; c2++) s += part[((size_t)b * 16 + c2) * 512 + d];
    out[(size_t)b * 512 + d] = s;
}

// ---------------------------------------------------------------------------
// Launch  (attn_mma is the 4th launch -> lands in the ncu profiled slot)
// ---------------------------------------------------------------------------
extern "C" void kernel_launch(void* const* d_in, const int* in_sizes, int n_in,
                              void* d_out, int out_size)
{
    const float* hid  = (const float*)d_in[0];
    const float* E    = (const float*)d_in[1];
    const float* W    = (const float*)d_in[2];
    const float* U    = (const float*)d_in[3];
    const float* V    = (const float*)d_in[4];
    const float* bias = (const float*)d_in[5];
    const float* Wa   = (const float*)d_in[6];
    const float* ba   = (const float*)d_in[7];

    float* out_o = (float*)d_out;
    float* out_a = (float*)d_out + BB * DD;

    float *P, *c, *cijp, *part;
    __half* BhT;
    cudaGetSymbolAddress((void**)&P,    g_P);
    cudaGetSymbolAddress((void**)&c,    g_c);
    cudaGetSymbolAddress((void**)&BhT,  g_BhT);
    cudaGetSymbolAddress((void**)&cijp, g_cij);
    cudaGetSymbolAddress((void**)&part, g_part);

    cudaFuncSetAttribute(attn_mma, cudaFuncAttributeMaxDynamicSharedMemorySize, SMEM_BYTES);

    rowgemm16<<<BB / 16, 512>>>(hid, W, bias, P);     // 1: P = hid@W + bias
    rowgemm16<<<BB / 16, 512>>>(P, Wa, ba, c);        // 2: c = P@Wa + ba
    rowgemmMh<<<DD / 16, 512>>>(U, Wa, BhT);          // 3: M^T fp16 = (U@Wa)^T

    attn_mma<<<(BB * TT) / 128, 256, SMEM_BYTES>>>(E, BhT, c, V, cijp);  // 4 (profiled)

    softmax_k<<<BB, 256>>>(cijp, out_a);
    wsum_partial<<<dim3(BB, 16), 512>>>(E, out_a, part);
    wsum_reduce<<<BB, 512>>>(part, out_o);
}